// round 14
// baseline (speedup 1.0000x reference)
#include <cuda_runtime.h>
#include <cuda_fp16.h>
#include <cstdint>

// Problem constants
#define NL   8
#define NH   512
#define NK   16
#define NIN  512
#define NB   8192
#define NR   16        // batch rows per block (8 row-pairs, half2 packed)
#define NRP  8
#define WSTORE (NIN + (NL-1)*NH)   // 4096 stored columns (max gathered idx = 4095)
#define VST  8         // column stride in half2 words: col c -> bank octet (c & 3)

// staged table: per (l,warp) 1536B contiguous: 16 rows x 24 words
// (16 pre-scaled byte offsets + 8 half2 weight pairs); pass p = bytes [p*384, p*384+384)
#define STG_WARP  1536
#define STG_BUF   (32*STG_WARP)                // 49152 B per buffer
#define SMEM_BYTES (WSTORE*VST*4 + 2*STG_BUF)  // 131072 + 98304 = 229376 <= 232448

// packed table, warp-blocked: per (l,warp): 16 rows x 24 u32 (96B rows, contiguous)
// row layout: words 0..15 = idx*32 (byte offsets); words 16..23 = half2(w[2t],w[2t+1])
__device__ __align__(16) unsigned int g_cmb[NL*32*384];

// ---------------- scheduling pre-kernel (unchanged from R13) ----------------
__global__ void sched_kernel(const int* __restrict__ link_idx,
                             const float* __restrict__ weights)
{
    __shared__ int sidx_s[128*16];
    __shared__ int swt_s [128*16];
    __shared__ unsigned int scr[127*33 + 32];   // [slot 0..127][w 0..31], stride 33

    const int tid = threadIdx.x;                 // 0..31
    const int bid = blockIdx.x;                  // 0..31
    const int l   = bid >> 2;
    const int p   = bid & 3;

    {
        const int base = (l * NH + p * 128) * NK;          // 2048 ints per table
        const int4* gi = (const int4*)(link_idx + base);
        const int4* gw = (const int4*)((const int*)weights + base);
        #pragma unroll
        for (int i = tid; i < 512; i += 32) {
            ((int4*)sidx_s)[i] = gi[i];
            ((int4*)swt_s)[i]  = gw[i];
        }
    }
    __syncthreads();

    const int rowb = tid * 4;

    unsigned m00=0,m01=0,m02=0,m03=0, m10=0,m11=0,m12=0,m13=0;
    unsigned m20=0,m21=0,m22=0,m23=0, m30=0,m31=0,m32=0,m33=0;
#define BUILD(J, A, B, C, D) { \
    const int* row = sidx_s + (rowb + J) * 16; \
    _Pragma("unroll") for (int k = 0; k < 16; k++) { \
        int rr = row[k] & 3; unsigned bit = 1u << k; \
        A |= (rr == 0) ? bit : 0u; B |= (rr == 1) ? bit : 0u; \
        C |= (rr == 2) ? bit : 0u; D |= (rr == 3) ? bit : 0u; } }
    BUILD(0, m00,m01,m02,m03) BUILD(1, m10,m11,m12,m13)
    BUILD(2, m20,m21,m22,m23) BUILD(3, m30,m31,m32,m33)
#undef BUILD

    for (int t = 0; t < 16; t++) {
        unsigned claimed = 0;
#define STEP(J, A, B, C, D) { \
    int c0=__popc(A), c1=__popc(B), c2=__popc(C), c3=__popc(D); \
    int s0 = c0 ? c0 + ((claimed & 1u) ? 0 : 16) : -1; \
    int s1 = c1 ? c1 + ((claimed & 2u) ? 0 : 16) : -1; \
    int s2 = c2 ? c2 + ((claimed & 4u) ? 0 : 16) : -1; \
    int s3 = c3 ? c3 + ((claimed & 8u) ? 0 : 16) : -1; \
    int bests = s0, bestr = 0; \
    if (s1 > bests) { bests = s1; bestr = 1; } \
    if (s2 > bests) { bests = s2; bestr = 2; } \
    if (s3 > bests) { bests = s3; bestr = 3; } \
    unsigned cur = (bestr==0) ? A : (bestr==1) ? B : (bestr==2) ? C : D; \
    int kk = __ffs(cur) - 1; cur &= cur - 1u; \
    A = (bestr==0) ? cur : A; B = (bestr==1) ? cur : B; \
    C = (bestr==2) ? cur : C; D = (bestr==3) ? cur : D; \
    claimed |= 1u << bestr; \
    const int src = (rowb + J) * 16 + kk; \
    scr[(J*32 + t)      * 33 + tid] = (unsigned)sidx_s[src]; \
    scr[(J*32 + 16 + t) * 33 + tid] = (unsigned)swt_s[src]; }
        STEP(0, m00,m01,m02,m03) STEP(1, m10,m11,m12,m13)
        STEP(2, m20,m21,m22,m23) STEP(3, m30,m31,m32,m33)
#undef STEP
    }
    __syncthreads();

    #pragma unroll 1
    for (int wq = 0; wq < 32; wq++) {
        unsigned int* dst = g_cmb + (l*32 + wq)*384 + p*96;
        #pragma unroll
        for (int r = 0; r < 3; r++) {
            int wi  = r*32 + tid;          // word 0..95
            int row = wi / 24;             // J (0..3)
            int pos = wi % 24;
            unsigned val;
            if (pos < 16) {                // pre-scaled byte offset for step t=pos
                val = scr[(row*32 + pos)*33 + wq] << 5;     // idx * 32
            } else {                       // weight pair (t=2k, 2k+1) as half2
                int k = pos - 16;
                unsigned a = scr[(row*32 + 16 + 2*k    )*33 + wq];
                unsigned b = scr[(row*32 + 16 + 2*k + 1)*33 + wq];
                __half ha = __float2half_rn(__uint_as_float(a));
                __half hb = __float2half_rn(__uint_as_float(b));
                val = (unsigned)__half_as_ushort(ha)
                    | ((unsigned)__half_as_ushort(hb) << 16);
            }
            dst[wi] = val;                 // coalesced STG.32
        }
    }
}

__device__ __forceinline__ float fast_sigmoid(float z) {
    float t;
    asm("tanh.approx.f32 %0, %1;" : "=f"(t) : "f"(0.5f * z));
    return fmaf(0.5f, t, 0.5f);
}

// ---------------- main fused kernel (shfl-distributed table) ----------------
__global__ __launch_bounds__(1024, 1)
void ffn_kernel(const float* __restrict__ x,
                const float* __restrict__ bias,
                float*       __restrict__ out)
{
    extern __shared__ __half2 smem2[];
    __half2* vals2 = smem2;                               // [4096 cols][8 rp], stride 8
    char*    stage = (char*)(smem2 + WSTORE * VST);       // 2 x 48KB staging buffers

    const unsigned int stage_u32 =
        (unsigned int)__cvta_generic_to_shared(stage);

    const int tid  = threadIdx.x;
    const int lane = tid & 31;
    const int warp = tid >> 5;
    const int rp   = lane & 7;          // row-pair 0..7
    const int hsub = lane >> 3;         // 0..3
    const int r0   = blockIdx.x * NR;
    const int cb   = hsub * 6;          // chunk base: row hsub starts at uint4 #6*hsub

    // per-thread value base: gathers read *(half2*)(vbase + staged_byte_offset)
    const char* vbase = (const char*)vals2 + rp * 4;

    // warp-private prefetch of one layer's packed table (1536B contiguous)
#define PREFETCH(L, BUF) { \
    const char* src = (const char*)(g_cmb + (size_t)((L)*32 + warp) * 384); \
    const unsigned int dstbase = stage_u32 + (BUF)*STG_BUF + warp*STG_WARP; \
    _Pragma("unroll") for (int c = 0; c < 3; c++) { \
        int c2 = (c*32 + lane) * 16; \
        asm volatile("cp.async.ca.shared.global [%0], [%1], 16;" \
                     :: "r"(dstbase + c2), "l"(src + c2)); } \
    asm volatile("cp.async.commit_group;" ::: "memory"); }

    PREFETCH(0, 0)

    // ---- x tile: (c, pp) mapping -> conflict-free STS ----
    #pragma unroll
    for (int i = tid; i < NRP * NIN; i += 1024) {         // 4096 half2
        int c  = i >> 3;
        int pp = i & 7;
        float a = x[(long)(r0 + 2*pp    ) * NIN + c];
        float b = x[(long)(r0 + 2*pp + 1) * NIN + c];
        vals2[c * VST + pp] = __floats2half2_rn(a, b);
    }

    int width = NIN;
    #pragma unroll 1
    for (int l = 0; l < NL; l++) {
        const int buf = l & 1;
        if (l < NL - 1) {
            PREFETCH(l + 1, buf ^ 1)                       // hide behind barrier+compute
            __syncthreads();                               // prev layer's values visible
            asm volatile("cp.async.wait_group 1;" ::: "memory");
        } else {
            __syncthreads();
            asm volatile("cp.async.wait_group 0;" ::: "memory");
        }
        __syncwarp();

        const float* brow = bias + l * NH;
        const bool last = (l == NL - 1);
        const char* wblk = stage + buf*STG_BUF + warp*STG_WARP;

        #pragma unroll
        for (int p = 0; p < 4; p++) {
            const int h = p * 128 + warp * 4 + hsub;

            // lanes 0..23 each load one distinct uint4 of this pass's 384B table
            // (1 LDS.128, 3 conflict-free wavefronts), then shfl-distribute.
            uint4 V;
            if (lane < 24)
                V = *(const uint4*)(wblk + p*384 + lane*16);

#define SH(comp, ch) __shfl_sync(0xffffffffu, (comp), (ch))
            // offsets: word row*24+t -> chunk cb+(t>>2), component t&3 (24 % 4 == 0)
            unsigned o0  = SH(V.x, cb    ), o1  = SH(V.y, cb    ),
                     o2  = SH(V.z, cb    ), o3  = SH(V.w, cb    );
            unsigned o4  = SH(V.x, cb + 1), o5  = SH(V.y, cb + 1),
                     o6  = SH(V.z, cb + 1), o7  = SH(V.w, cb + 1);
            unsigned o8  = SH(V.x, cb + 2), o9  = SH(V.y, cb + 2),
                     o10 = SH(V.z, cb + 2), o11 = SH(V.w, cb + 2);
            unsigned o12 = SH(V.x, cb + 3), o13 = SH(V.y, cb + 3),
                     o14 = SH(V.z, cb + 3), o15 = SH(V.w, cb + 3);
            // weight pairs: word row*24+16+k -> chunk cb+4+(k>>2), component k&3
            unsigned wA = SH(V.x, cb + 4), wB = SH(V.y, cb + 4),
                     wC = SH(V.z, cb + 4), wD = SH(V.w, cb + 4);
            unsigned wE = SH(V.x, cb + 5), wF = SH(V.y, cb + 5),
                     wG = SH(V.z, cb + 5), wH = SH(V.w, cb + 5);
#undef SH

            float ax = 0.0f, ay = 0.0f;

            // sub-chain of 4 fp16 HFMA2 steps, flushed into fp32 (keeps rounding small)
#define LDV(off) (*(const __half2*)(vbase + (off)))
#define SUBCHAIN(q0, q1, q2, q3, wlo, whi) { \
    __half2 hw0 = *(const __half2*)&(wlo); \
    __half2 hw1 = *(const __half2*)&(whi); \
    __half2 hacc = __hmul2(LDV(q0), __half2half2(__low2half(hw0))); \
    hacc = __hfma2(LDV(q1), __half2half2(__high2half(hw0)), hacc); \
    hacc = __hfma2(LDV(q2), __half2half2(__low2half(hw1)),  hacc); \
    hacc = __hfma2(LDV(q3), __half2half2(__high2half(hw1)), hacc); \
    float2 f = __half22float2(hacc); ax += f.x; ay += f.y; }

            SUBCHAIN(o0,  o1,  o2,  o3,  wA, wB)
            SUBCHAIN(o4,  o5,  o6,  o7,  wC, wD)
            SUBCHAIN(o8,  o9,  o10, o11, wE, wF)
            SUBCHAIN(o12, o13, o14, o15, wG, wH)
#undef SUBCHAIN
#undef LDV

            float b0 = __ldg(brow + h);
            float ox = fast_sigmoid(ax + b0);
            float oy = fast_sigmoid(ay + b0);

            if (!last) {
                // h mod 4 = hsub -> distinct octets x 8 rp -> conflict-free store
                vals2[(width + h) * VST + rp] = __floats2half2_rn(ox, oy);
            } else {
                out[(long)(r0 + 2*rp    ) * NH + h] = ox;
                out[(long)(r0 + 2*rp + 1) * NH + h] = oy;
            }
        }
        width += NH;
    }
#undef PREFETCH
}

extern "C" void kernel_launch(void* const* d_in, const int* in_sizes, int n_in,
                              void* d_out, int out_size)
{
    const float* x        = (const float*)d_in[0];   // (8192, 512) f32
    const int*   link_idx = (const int*)d_in[1];     // (8, 512, 16) i32
    const float* weights  = (const float*)d_in[2];   // (8, 512, 16) f32
    const float* bias     = (const float*)d_in[3];   // (8, 512) f32
    float*       out      = (float*)d_out;           // (8192, 512) f32

    cudaFuncSetAttribute(ffn_kernel,
                         cudaFuncAttributeMaxDynamicSharedMemorySize, SMEM_BYTES);

    sched_kernel<<<32, 32>>>(link_idx, weights);
    ffn_kernel<<<NB / NR, 1024, SMEM_BYTES>>>(x, bias, out);
}

// round 15
// speedup vs baseline: 1.1127x; 1.1127x over previous
#include <cuda_runtime.h>
#include <cuda_fp16.h>
#include <cstdint>

// Problem constants
#define NL   8
#define NH   512
#define NK   16
#define NIN  512
#define NB   8192
#define NR   8         // batch rows per block (4 row-pairs, half2 packed)
#define NRP  4
#define WSTORE (NIN + (NL-1)*NH)   // 4096 stored columns
#define VST  4         // column stride in half2 words: col c -> bank quad (c & 7)

// staged row (one h): 16 u16 offsets (32B) + 16 f16 weights (32B) = 64B, stride 80.
// rows j*80 mod 128 = {0,80,32,112,64,16,96,48} -> 8 distinct bank quads.
#define STG_ROW   80
#define STG_WARP  (32*STG_ROW)                 // 2560 B per warp (32 h rows)
#define STG_BUF   (16*STG_WARP)                // 40960 B (16 warps), single buffer
#define SMEM_BYTES (WSTORE*VST*4 + STG_BUF)    // 65536 + 40960 = 106496 (2 blocks/SM)

// packed table: per (l,warp): 32 rows x 16 u32 (64B rows contiguous), row = p*8 + hj
// words 0..7 = u16 offset pairs (idx*16); words 8..15 = half2 weight pairs
__device__ __align__(16) unsigned int g_cmb[NL*16*512];

#define SCHED_SMEM ((4096 + 4096 + 256*33 + 32) * 4)   // idx + w + scratch

// ---------------- scheduling pre-kernel (mod-8 residue matching) ----------------
// 16 blocks x 32 threads; thread = one oct (8 h). Permutes each h's 16 (idx,w)
// pairs so step t uses 8 columns with pairwise-distinct (idx mod 8)
// -> each ffn gather = 1 smem wavefront (128B).
__global__ void sched_kernel(const int* __restrict__ link_idx,
                             const float* __restrict__ weights)
{
    extern __shared__ int ssch[];
    int* sidx_s = ssch;                    // [256*16]
    int* swt_s  = ssch + 4096;             // [256*16]
    unsigned int* scr = (unsigned int*)(ssch + 8192);   // [256 slots][33]

    const int tid = threadIdx.x;                 // 0..31
    const int bid = blockIdx.x;                  // 0..15
    const int q   = bid * 32 + tid;              // oct 0..511
    const int l   = q >> 6;
    const int rem = q & 63;
    const int p   = rem >> 4;
    const int w   = rem & 15;
    const int lrow = (p & 1) * 128 + w * 8;      // local row base within block slice

    // stage this block's 256 h-rows (coalesced): layer l, h in [ (bid&1)*256, +256 )
    {
        const int base = (l * NH + (bid & 1) * 256) * NK;   // 4096 ints per table
        const int4* gi = (const int4*)(link_idx + base);
        const int4* gw = (const int4*)((const int*)weights + base);
        #pragma unroll
        for (int i = tid; i < 1024; i += 32) {
            ((int4*)sidx_s)[i] = gi[i];
            ((int4*)swt_s)[i]  = gw[i];
        }
    }
    __syncthreads();

    // per-j class masks: 8 classes as u16 halves packed 2-per-reg (4 regs per j)
    unsigned M0[8], M1[8], M2[8], M3[8];   // constant-indexed only (unrolled)
#define BUILDJ(J) { \
    const int* row = sidx_s + (lrow + (J)) * 16; \
    unsigned a0=0,a1=0,a2=0,a3=0; \
    _Pragma("unroll") for (int k = 0; k < 16; k++) { \
        int r = row[k] & 7; unsigned bit = 1u << k; \
        a0 |= (r==0)?bit:0u; a0 |= (r==1)?(bit<<16):0u; \
        a1 |= (r==2)?bit:0u; a1 |= (r==3)?(bit<<16):0u; \
        a2 |= (r==4)?bit:0u; a2 |= (r==5)?(bit<<16):0u; \
        a3 |= (r==6)?bit:0u; a3 |= (r==7)?(bit<<16):0u; } \
    M0[J]=a0; M1[J]=a1; M2[J]=a2; M3[J]=a3; }
    BUILDJ(0) BUILDJ(1) BUILDJ(2) BUILDJ(3)
    BUILDJ(4) BUILDJ(5) BUILDJ(6) BUILDJ(7)
#undef BUILDJ

    for (int t = 0; t < 16; t++) {
        unsigned claimed = 0;
#define STEP(J) { \
    unsigned m0 = M0[J] & 0xffffu, m1 = M0[J] >> 16; \
    unsigned m2 = M1[J] & 0xffffu, m3 = M1[J] >> 16; \
    unsigned m4 = M2[J] & 0xffffu, m5 = M2[J] >> 16; \
    unsigned m6 = M3[J] & 0xffffu, m7 = M3[J] >> 16; \
    int c0=__popc(m0),c1=__popc(m1),c2=__popc(m2),c3=__popc(m3); \
    int c4=__popc(m4),c5=__popc(m5),c6=__popc(m6),c7=__popc(m7); \
    int s0 = (c0 ? c0 + ((claimed&  1u)?0:16) : 0) << 3 | 0; \
    int s1 = (c1 ? c1 + ((claimed&  2u)?0:16) : 0) << 3 | 1; \
    int s2 = (c2 ? c2 + ((claimed&  4u)?0:16) : 0) << 3 | 2; \
    int s3 = (c3 ? c3 + ((claimed&  8u)?0:16) : 0) << 3 | 3; \
    int s4 = (c4 ? c4 + ((claimed& 16u)?0:16) : 0) << 3 | 4; \
    int s5 = (c5 ? c5 + ((claimed& 32u)?0:16) : 0) << 3 | 5; \
    int s6 = (c6 ? c6 + ((claimed& 64u)?0:16) : 0) << 3 | 6; \
    int s7 = (c7 ? c7 + ((claimed&128u)?0:16) : 0) << 3 | 7; \
    int a = max(s0,s1), b = max(s2,s3), c = max(s4,s5), d = max(s6,s7); \
    int e = max(a,b),   f = max(c,d); \
    int best = max(e,f); \
    int bc = best & 7; \
    unsigned ma = (bc & 4) ? ((bc & 2) ? ((bc & 1) ? m7 : m6) : ((bc & 1) ? m5 : m4)) \
                           : ((bc & 2) ? ((bc & 1) ? m3 : m2) : ((bc & 1) ? m1 : m0)); \
    int kk = __ffs(ma) - 1; \
    unsigned nm = ma & (ma - 1u); \
    claimed |= 1u << bc; \
    M0[J] = (bc==0) ? (M0[J] & 0xffff0000u) | nm \
          : (bc==1) ? (M0[J] & 0x0000ffffu) | (nm << 16) : M0[J]; \
    M1[J] = (bc==2) ? (M1[J] & 0xffff0000u) | nm \
          : (bc==3) ? (M1[J] & 0x0000ffffu) | (nm << 16) : M1[J]; \
    M2[J] = (bc==4) ? (M2[J] & 0xffff0000u) | nm \
          : (bc==5) ? (M2[J] & 0x0000ffffu) | (nm << 16) : M2[J]; \
    M3[J] = (bc==6) ? (M3[J] & 0xffff0000u) | nm \
          : (bc==7) ? (M3[J] & 0x0000ffffu) | (nm << 16) : M3[J]; \
    const int src = (lrow + (J)) * 16 + kk; \
    scr[((J)*32 + t)      * 33 + tid] = (unsigned)sidx_s[src]; \
    scr[((J)*32 + 16 + t) * 33 + tid] = (unsigned)swt_s[src]; }
        STEP(0) STEP(1) STEP(2) STEP(3) STEP(4) STEP(5) STEP(6) STEP(7)
#undef STEP
    }
    __syncthreads();

    // coalesced packed copy-out: oct wq -> g_cmb[((l*16+w)*32 + p*8)*16 ..+127]
    #pragma unroll 1
    for (int wq = 0; wq < 32; wq++) {
        int q2 = bid * 32 + wq;
        int l2 = q2 >> 6, rem2 = q2 & 63;
        int p2 = rem2 >> 4, w2 = rem2 & 15;
        unsigned int* dst = g_cmb + ((l2*16 + w2)*32 + p2*8) * 16;
        #pragma unroll
        for (int r = 0; r < 4; r++) {
            int wi  = r*32 + tid;          // word 0..127
            int j   = wi >> 4;
            int pos = wi & 15;
            unsigned val;
            if (pos < 8) {                 // u16 offset pair (idx*16) for t=2*pos,2*pos+1
                unsigned a = scr[(j*32 + 2*pos    )*33 + wq];
                unsigned b = scr[(j*32 + 2*pos + 1)*33 + wq];
                val = (a << 4) | (b << 20);
            } else {                       // weight half2 pair for t=2k,2k+1
                int k = pos - 8;
                unsigned a = scr[(j*32 + 16 + 2*k    )*33 + wq];
                unsigned b = scr[(j*32 + 16 + 2*k + 1)*33 + wq];
                __half ha = __float2half_rn(__uint_as_float(a));
                __half hb = __float2half_rn(__uint_as_float(b));
                val = (unsigned)__half_as_ushort(ha)
                    | ((unsigned)__half_as_ushort(hb) << 16);
            }
            dst[wi] = val;                 // coalesced STG.32
        }
    }
}

__device__ __forceinline__ float fast_sigmoid(float z) {
    float t;
    asm("tanh.approx.f32 %0, %1;" : "=f"(t) : "f"(0.5f * z));
    return fmaf(0.5f, t, 0.5f);
}

// ---------------- main fused kernel: 512 thr, 2 blocks/SM, 8h x 4rp warps ----------------
__global__ __launch_bounds__(512, 2)
void ffn_kernel(const float* __restrict__ x,
                const float* __restrict__ bias,
                float*       __restrict__ out)
{
    extern __shared__ __half2 smem2[];
    __half2* vals2 = smem2;                               // [4096 cols][4 rp], stride 4
    char*    stage = (char*)(smem2 + WSTORE * VST);       // 16 warp-private 2560B blocks

    const unsigned int stage_u32 =
        (unsigned int)__cvta_generic_to_shared(stage);

    const int tid  = threadIdx.x;
    const int lane = tid & 31;
    const int warp = tid >> 5;          // 0..15
    const int rp   = lane & 3;          // row-pair 0..3
    const int hj   = lane >> 2;         // 0..7
    const int r0   = blockIdx.x * NR;

    // per-thread value base: gathers read *(half2*)(vbase + u16_offset)
    const char* vbase = (const char*)vals2 + rp * 4;

    // warp-private prefetch of one layer's packed table (2048B -> 128 16B chunks)
#define PREFETCH(L) { \
    const char* src = (const char*)(g_cmb + (size_t)((L)*16 + warp) * 512); \
    const unsigned int dstbase = stage_u32 + warp * STG_WARP; \
    _Pragma("unroll") for (int c = 0; c < 4; c++) { \
        int c2 = c*32 + lane; \
        unsigned int dst = dstbase + (c2 >> 2) * STG_ROW + (c2 & 3) * 16; \
        asm volatile("cp.async.ca.shared.global [%0], [%1], 16;" \
                     :: "r"(dst), "l"(src + c2*16)); } \
    asm volatile("cp.async.commit_group;" ::: "memory"); }

    PREFETCH(0)

    // ---- x tile: 4 row-pairs x 512 cols; 4-lane groups per col, cols distinct mod 8 ----
    #pragma unroll
    for (int i = tid; i < NRP * NIN; i += 512) {          // 2048 half2
        int c  = i >> 2;
        int pp = i & 3;
        float a = x[(long)(r0 + 2*pp    ) * NIN + c];
        float b = x[(long)(r0 + 2*pp + 1) * NIN + c];
        vals2[c * VST + pp] = __floats2half2_rn(a, b);
    }

    int width = NIN;
    #pragma unroll 1
    for (int l = 0; l < NL; l++) {
        __syncthreads();                                  // prev layer's values visible
        asm volatile("cp.async.wait_group 0;" ::: "memory");
        __syncwarp();

        const float* brow = bias + l * NH;
        const bool last = (l == NL - 1);
        const char* wblk = stage + warp * STG_WARP;

        #pragma unroll
        for (int p = 0; p < 4; p++) {
            const int h = p * 128 + warp * 8 + hj;
            const char* rowp = wblk + (p*8 + hj) * STG_ROW;

            // 2 offset LDS.128 + 2 weight LDS.128; 8 rows on distinct bank quads
            uint4 oa = *(const uint4*)(rowp);        // u16 offset pairs t0..7
            uint4 ob = *(const uint4*)(rowp + 16);   // t8..15
            uint4 wa = *(const uint4*)(rowp + 32);   // weight half2 pairs t0..7
            uint4 wb = *(const uint4*)(rowp + 48);   // t8..15

            float ax = 0.0f, ay = 0.0f;

            // sub-chain of 4 fp16 HFMA2 steps, flushed into fp32
#define LDV(off) (*(const __half2*)(vbase + (off)))
#define SUBCHAIN(ow0, ow1, wlo, whi) { \
    __half2 hw0 = *(const __half2*)&(wlo); \
    __half2 hw1 = *(const __half2*)&(whi); \
    __half2 hacc = __hmul2(LDV((ow0) & 0xffffu), __half2half2(__low2half(hw0))); \
    hacc = __hfma2(LDV((ow0) >> 16),    __half2half2(__high2half(hw0)), hacc); \
    hacc = __hfma2(LDV((ow1) & 0xffffu), __half2half2(__low2half(hw1)),  hacc); \
    hacc = __hfma2(LDV((ow1) >> 16),    __half2half2(__high2half(hw1)), hacc); \
    float2 f = __half22float2(hacc); ax += f.x; ay += f.y; }

            SUBCHAIN(oa.x, oa.y, wa.x, wa.y)
            SUBCHAIN(oa.z, oa.w, wa.z, wa.w)
            SUBCHAIN(ob.x, ob.y, wb.x, wb.y)
            SUBCHAIN(ob.z, ob.w, wb.z, wb.w)
#undef SUBCHAIN
#undef LDV

            float b0 = __ldg(brow + h);
            float ox = fast_sigmoid(ax + b0);
            float oy = fast_sigmoid(ay + b0);

            if (!last) {
                // h mod 8 = hj -> 8 distinct quads x 4 rp -> conflict-free store
                vals2[(width + h) * VST + rp] = __floats2half2_rn(ox, oy);
            } else {
                out[(long)(r0 + 2*rp    ) * NH + h] = ox;
                out[(long)(r0 + 2*rp + 1) * NH + h] = oy;
            }
        }

        // prefetch next layer AFTER this layer's table regs are consumed
        if (l < NL - 1) PREFETCH(l + 1)
        width += NH;
    }
#undef PREFETCH
}

extern "C" void kernel_launch(void* const* d_in, const int* in_sizes, int n_in,
                              void* d_out, int out_size)
{
    const float* x        = (const float*)d_in[0];   // (8192, 512) f32
    const int*   link_idx = (const int*)d_in[1];     // (8, 512, 16) i32
    const float* weights  = (const float*)d_in[2];   // (8, 512, 16) f32
    const float* bias     = (const float*)d_in[3];   // (8, 512) f32
    float*       out      = (float*)d_out;           // (8192, 512) f32

    cudaFuncSetAttribute(ffn_kernel,
                         cudaFuncAttributeMaxDynamicSharedMemorySize, SMEM_BYTES);
    cudaFuncSetAttribute(sched_kernel,
                         cudaFuncAttributeMaxDynamicSharedMemorySize, SCHED_SMEM);

    sched_kernel<<<16, 32, SCHED_SMEM>>>(link_idx, weights);
    ffn_kernel<<<NB / NR, 512, SMEM_BYTES>>>(x, bias, out);
}

// round 16
// speedup vs baseline: 1.3007x; 1.1690x over previous
#include <cuda_runtime.h>
#include <cuda_fp16.h>
#include <cstdint>

// Problem constants
#define NL   8
#define NH   512
#define NK   16
#define NIN  512
#define NB   8192
#define NR   8         // batch rows per block (4 row-pairs, half2 packed)
#define NRP  4
#define WSTORE (NIN + (NL-1)*NH)   // 4096 stored columns
#define VST  4         // column stride in half2 words: col c -> bank quad (c & 7)

// staged row (one h): 16 u16 offsets (32B) + 16 f16 weights (32B) = 64B, stride 80.
// rows j*80 mod 128 = {0,80,32,112,64,16,96,48} -> 8 distinct bank quads.
#define STG_ROW   80
#define STG_WARP  (32*STG_ROW)                 // 2560 B per warp (32 h rows)
#define STG_BUF   (16*STG_WARP)                // 40960 B (16 warps), single buffer
#define SMEM_BYTES (WSTORE*VST*4 + STG_BUF)    // 65536 + 40960 = 106496 (2 blocks/SM)

// packed table: per (l,warp): 32 rows x 16 u32 (64B rows contiguous), row = p*8 + hj
// words 0..7 = u16 offset pairs (idx*16); words 8..15 = half2 weight pairs
__device__ __align__(16) unsigned int g_cmb[NL*16*512];

// ---------------- scheduling pre-kernel (lane-parallel greedy) ----------------
// 128 blocks x 32 threads: block = (l, warp16), lane = row r = p*8 + hj.
// The 8 lanes of each oct run the greedy cooperatively: per step t, lane j picks
// a class (idx mod 8) not yet claimed this step, relayed via shfl. Result: step t
// uses 8 columns with (nearly always) pairwise-distinct bank quads -> ffn gather
// = 1 smem wavefront.
__global__ void sched_kernel(const int* __restrict__ link_idx,
                             const float* __restrict__ weights)
{
    __shared__ int sidx_s[32*16];            // [row][k]
    __shared__ int swt_s [32*16];
    __shared__ unsigned cmask_s[32*9];       // [row][class], stride 9
    __shared__ unsigned char pk_s[32*16];    // picked k per (row, t)

    const int tid = threadIdx.x;             // 0..31 = local row r
    const int bid = blockIdx.x;              // 0..127
    const int l   = bid >> 4;
    const int w   = bid & 15;

    // stage the 32 rows this ffn warp owns: h = p*128 + w*8 + hj
    #pragma unroll
    for (int p = 0; p < 4; p++) {
        const int base = (l*NH + p*128 + w*8) * NK;   // 128 ints (8 rows) contiguous
        ((int4*)(sidx_s + p*128))[tid] = ((const int4*)(link_idx + base))[tid];
        ((int4*)(swt_s  + p*128))[tid] = ((const int4*)((const int*)weights + base))[tid];
    }
    __syncthreads();

    // build class masks for own row (registers, constant-indexed)
    unsigned m0=0,m1=0,m2=0,m3=0,m4=0,m5=0,m6=0,m7=0;
    {
        const int* row = sidx_s + tid*16;
        #pragma unroll
        for (int k = 0; k < 16; k++) {
            int c = row[k] & 7; unsigned b = 1u << k;
            m0 |= (c==0)?b:0u; m1 |= (c==1)?b:0u; m2 |= (c==2)?b:0u; m3 |= (c==3)?b:0u;
            m4 |= (c==4)?b:0u; m5 |= (c==5)?b:0u; m6 |= (c==6)?b:0u; m7 |= (c==7)?b:0u;
        }
    }
    cmask_s[tid*9+0]=m0; cmask_s[tid*9+1]=m1; cmask_s[tid*9+2]=m2; cmask_s[tid*9+3]=m3;
    cmask_s[tid*9+4]=m4; cmask_s[tid*9+5]=m5; cmask_s[tid*9+6]=m6; cmask_s[tid*9+7]=m7;

    unsigned avail  = (m0?1u:0u)|(m1?2u:0u)|(m2?4u:0u)|(m3?8u:0u)
                    | (m4?16u:0u)|(m5?32u:0u)|(m6?64u:0u)|(m7?128u:0u);
    unsigned avail2 = (__popc(m0)>1?1u:0u)|(__popc(m1)>1?2u:0u)
                    | (__popc(m2)>1?4u:0u)|(__popc(m3)>1?8u:0u)
                    | (__popc(m4)>1?16u:0u)|(__popc(m5)>1?32u:0u)
                    | (__popc(m6)>1?64u:0u)|(__popc(m7)>1?128u:0u);

    const int gbase = tid & 24;              // oct base lane

    #pragma unroll 1
    for (int t = 0; t < 16; t++) {
        unsigned cl = 0;
        #pragma unroll
        for (int j = 0; j < 8; j++) {
            if ((tid & 7) == j) {
                unsigned un2 = avail2 & ~cl;
                unsigned un1 = avail  & ~cl;
                unsigned sel = un2 ? un2 : (un1 ? un1 : avail);
                int bc = __ffs(sel) - 1;
                cl |= 1u << bc;
                unsigned mk = cmask_s[tid*9 + bc];
                int kk = __ffs(mk) - 1;
                mk &= mk - 1u;
                cmask_s[tid*9 + bc] = mk;
                if (mk == 0u)          avail  &= ~(1u << bc);
                if (__popc(mk) == 1)   avail2 &= ~(1u << bc);
                pk_s[tid*16 + t] = (unsigned char)kk;
            }
            cl = __shfl_sync(0xffffffffu, cl, gbase + j);   // relay claimed set
        }
    }
    __syncthreads();

    // coalesced packed output: 512 words per (l, warp16)
    unsigned int* dst = g_cmb + (size_t)(l*16 + w) * 512;
    #pragma unroll
    for (int c = 0; c < 16; c++) {
        int wi  = c*32 + tid;                // 0..511
        int r   = wi >> 4;
        int pos = wi & 15;
        unsigned val;
        if (pos < 8) {                       // u16 offset pair for t=2*pos, 2*pos+1
            int k0 = pk_s[r*16 + 2*pos], k1 = pk_s[r*16 + 2*pos + 1];
            unsigned i0 = (unsigned)sidx_s[r*16 + k0];
            unsigned i1 = (unsigned)sidx_s[r*16 + k1];
            val = (i0 << 4) | (i1 << 20);    // byte offsets idx*16
        } else {                             // weight half2 pair for t=2k, 2k+1
            int k = pos - 8;
            int k0 = pk_s[r*16 + 2*k], k1 = pk_s[r*16 + 2*k + 1];
            __half h0 = __float2half_rn(__int_as_float(swt_s[r*16 + k0]));
            __half h1 = __float2half_rn(__int_as_float(swt_s[r*16 + k1]));
            val = (unsigned)__half_as_ushort(h0)
                | ((unsigned)__half_as_ushort(h1) << 16);
        }
        dst[wi] = val;                       // coalesced STG.32
    }
}

__device__ __forceinline__ float fast_sigmoid(float z) {
    float t;
    asm("tanh.approx.f32 %0, %1;" : "=f"(t) : "f"(0.5f * z));
    return fmaf(0.5f, t, 0.5f);
}

// ---------------- main fused kernel (identical to R15's 100.4us version) ----------------
__global__ __launch_bounds__(512, 2)
void ffn_kernel(const float* __restrict__ x,
                const float* __restrict__ bias,
                float*       __restrict__ out)
{
    extern __shared__ __half2 smem2[];
    __half2* vals2 = smem2;                               // [4096 cols][4 rp], stride 4
    char*    stage = (char*)(smem2 + WSTORE * VST);       // 16 warp-private 2560B blocks

    const unsigned int stage_u32 =
        (unsigned int)__cvta_generic_to_shared(stage);

    const int tid  = threadIdx.x;
    const int lane = tid & 31;
    const int warp = tid >> 5;          // 0..15
    const int rp   = lane & 3;          // row-pair 0..3
    const int hj   = lane >> 2;         // 0..7
    const int r0   = blockIdx.x * NR;

    // per-thread value base: gathers read *(half2*)(vbase + u16_offset)
    const char* vbase = (const char*)vals2 + rp * 4;

    // warp-private prefetch of one layer's packed table (2048B -> 128 16B chunks)
#define PREFETCH(L) { \
    const char* src = (const char*)(g_cmb + (size_t)((L)*16 + warp) * 512); \
    const unsigned int dstbase = stage_u32 + warp * STG_WARP; \
    _Pragma("unroll") for (int c = 0; c < 4; c++) { \
        int c2 = c*32 + lane; \
        unsigned int dst = dstbase + (c2 >> 2) * STG_ROW + (c2 & 3) * 16; \
        asm volatile("cp.async.ca.shared.global [%0], [%1], 16;" \
                     :: "r"(dst), "l"(src + c2*16)); } \
    asm volatile("cp.async.commit_group;" ::: "memory"); }

    PREFETCH(0)

    // ---- x tile: 4 row-pairs x 512 cols ----
    #pragma unroll
    for (int i = tid; i < NRP * NIN; i += 512) {          // 2048 half2
        int c  = i >> 2;
        int pp = i & 3;
        float a = x[(long)(r0 + 2*pp    ) * NIN + c];
        float b = x[(long)(r0 + 2*pp + 1) * NIN + c];
        vals2[c * VST + pp] = __floats2half2_rn(a, b);
    }

    int width = NIN;
    #pragma unroll 1
    for (int l = 0; l < NL; l++) {
        __syncthreads();                                  // prev layer's values visible
        asm volatile("cp.async.wait_group 0;" ::: "memory");
        __syncwarp();

        const float* brow = bias + l * NH;
        const bool last = (l == NL - 1);
        const char* wblk = stage + warp * STG_WARP;

        #pragma unroll
        for (int p = 0; p < 4; p++) {
            const int h = p * 128 + warp * 8 + hj;
            const char* rowp = wblk + (p*8 + hj) * STG_ROW;

            // 2 offset LDS.128 + 2 weight LDS.128; 8 rows on distinct bank quads
            uint4 oa = *(const uint4*)(rowp);        // u16 offset pairs t0..7
            uint4 ob = *(const uint4*)(rowp + 16);   // t8..15
            uint4 wa = *(const uint4*)(rowp + 32);   // weight half2 pairs t0..7
            uint4 wb = *(const uint4*)(rowp + 48);   // t8..15

            float ax = 0.0f, ay = 0.0f;

            // sub-chain of 4 fp16 HFMA2 steps, flushed into fp32
#define LDV(off) (*(const __half2*)(vbase + (off)))
#define SUBCHAIN(ow0, ow1, wlo, whi) { \
    __half2 hw0 = *(const __half2*)&(wlo); \
    __half2 hw1 = *(const __half2*)&(whi); \
    __half2 hacc = __hmul2(LDV((ow0) & 0xffffu), __half2half2(__low2half(hw0))); \
    hacc = __hfma2(LDV((ow0) >> 16),    __half2half2(__high2half(hw0)), hacc); \
    hacc = __hfma2(LDV((ow1) & 0xffffu), __half2half2(__low2half(hw1)),  hacc); \
    hacc = __hfma2(LDV((ow1) >> 16),    __half2half2(__high2half(hw1)), hacc); \
    float2 f = __half22float2(hacc); ax += f.x; ay += f.y; }

            SUBCHAIN(oa.x, oa.y, wa.x, wa.y)
            SUBCHAIN(oa.z, oa.w, wa.z, wa.w)
            SUBCHAIN(ob.x, ob.y, wb.x, wb.y)
            SUBCHAIN(ob.z, ob.w, wb.z, wb.w)
#undef SUBCHAIN
#undef LDV

            float b0 = __ldg(brow + h);
            float ox = fast_sigmoid(ax + b0);
            float oy = fast_sigmoid(ay + b0);

            if (!last) {
                // h mod 8 = hj -> 8 distinct quads x 4 rp -> conflict-free store
                vals2[(width + h) * VST + rp] = __floats2half2_rn(ox, oy);
            } else {
                out[(long)(r0 + 2*rp    ) * NH + h] = ox;
                out[(long)(r0 + 2*rp + 1) * NH + h] = oy;
            }
        }

        // prefetch next layer AFTER this layer's table is consumed
        if (l < NL - 1) PREFETCH(l + 1)
        width += NH;
    }
#undef PREFETCH
}

extern "C" void kernel_launch(void* const* d_in, const int* in_sizes, int n_in,
                              void* d_out, int out_size)
{
    const float* x        = (const float*)d_in[0];   // (8192, 512) f32
    const int*   link_idx = (const int*)d_in[1];     // (8, 512, 16) i32
    const float* weights  = (const float*)d_in[2];   // (8, 512, 16) f32
    const float* bias     = (const float*)d_in[3];   // (8, 512) f32
    float*       out      = (float*)d_out;           // (8192, 512) f32

    cudaFuncSetAttribute(ffn_kernel,
                         cudaFuncAttributeMaxDynamicSharedMemorySize, SMEM_BYTES);

    sched_kernel<<<NL*16, 32>>>(link_idx, weights);
    ffn_kernel<<<NB / NR, 512, SMEM_BYTES>>>(x, bias, out);
}

// round 17
// speedup vs baseline: 1.3605x; 1.0460x over previous
#include <cuda_runtime.h>
#include <cuda_fp16.h>
#include <cstdint>

// Problem constants
#define NL   8
#define NH   512
#define NK   16
#define NIN  512
#define NB   8192
#define NR   8         // batch rows per block (4 row-pairs, half2 packed)
#define NRP  4
#define WSTORE (NIN + (NL-1)*NH)   // 4096 stored columns
#define VST  4         // column stride in half2 words: col c -> bank quad (c & 7)

// staged row (one h): 16 u16 offsets (32B) + 16 f16 weights (32B) = 64B, stride 80.
// rows j*80 mod 128 = {0,80,32,112,64,16,96,48} -> 8 distinct bank quads.
#define STG_ROW   80
#define STG_WARP  (32*STG_ROW)                 // 2560 B per warp (32 h rows)
#define STG_BUF   (16*STG_WARP)                // 40960 B (16 warps), single buffer
#define SMEM_BYTES (WSTORE*VST*4 + STG_BUF)    // 65536 + 40960 = 106496 (2 blocks/SM)

// packed table: per (l,warp): 32 rows x 16 u32 (64B rows contiguous), row = p*8 + hj
// words 0..7 = u16 offset pairs (idx*16); words 8..15 = half2 weight pairs
__device__ __align__(16) unsigned int g_cmb[NL*16*512];

// ---------------- scheduling pre-kernel (branchless lane-parallel greedy) ----------------
// 128 blocks x 32 threads: block = (l, warp16), lane = row r = p*8 + hj.
// The 8 lanes of each oct pick classes (idx mod 8) cooperatively per step t via a
// branch-free shfl relay: every lane computes a speculative pick from its own
// masks; the relay broadcasts the authoritative lane's claimed-set. Picks are
// bit-identical to the branchy version -> same permutation, same ffn numerics.
__global__ void sched_kernel(const int* __restrict__ link_idx,
                             const float* __restrict__ weights)
{
    __shared__ int sidx_s[32*16];            // [row][k]
    __shared__ int swt_s [32*16];
    __shared__ unsigned cmask_s[32*9];       // [row][class], stride 9
    __shared__ unsigned char pk_s[32*16];    // picked k per (row, t)

    const int tid = threadIdx.x;             // 0..31 = local row r
    const int bid = blockIdx.x;              // 0..127
    const int l   = bid >> 4;
    const int w   = bid & 15;

    // stage the 32 rows this ffn warp owns: h = p*128 + w*8 + hj
    #pragma unroll
    for (int p = 0; p < 4; p++) {
        const int base = (l*NH + p*128 + w*8) * NK;   // 128 ints (8 rows) contiguous
        ((int4*)(sidx_s + p*128))[tid] = ((const int4*)(link_idx + base))[tid];
        ((int4*)(swt_s  + p*128))[tid] = ((const int4*)((const int*)weights + base))[tid];
    }
    __syncthreads();

    // build class masks for own row (registers, constant-indexed)
    unsigned m0=0,m1=0,m2=0,m3=0,m4=0,m5=0,m6=0,m7=0;
    {
        const int* row = sidx_s + tid*16;
        #pragma unroll
        for (int k = 0; k < 16; k++) {
            int c = row[k] & 7; unsigned b = 1u << k;
            m0 |= (c==0)?b:0u; m1 |= (c==1)?b:0u; m2 |= (c==2)?b:0u; m3 |= (c==3)?b:0u;
            m4 |= (c==4)?b:0u; m5 |= (c==5)?b:0u; m6 |= (c==6)?b:0u; m7 |= (c==7)?b:0u;
        }
    }
    cmask_s[tid*9+0]=m0; cmask_s[tid*9+1]=m1; cmask_s[tid*9+2]=m2; cmask_s[tid*9+3]=m3;
    cmask_s[tid*9+4]=m4; cmask_s[tid*9+5]=m5; cmask_s[tid*9+6]=m6; cmask_s[tid*9+7]=m7;

    unsigned avail  = (m0?1u:0u)|(m1?2u:0u)|(m2?4u:0u)|(m3?8u:0u)
                    | (m4?16u:0u)|(m5?32u:0u)|(m6?64u:0u)|(m7?128u:0u);
    unsigned avail2 = (__popc(m0)>1?1u:0u)|(__popc(m1)>1?2u:0u)
                    | (__popc(m2)>1?4u:0u)|(__popc(m3)>1?8u:0u)
                    | (__popc(m4)>1?16u:0u)|(__popc(m5)>1?32u:0u)
                    | (__popc(m6)>1?64u:0u)|(__popc(m7)>1?128u:0u);

    const int gbase = tid & 24;              // oct base lane
    const int own   = tid & 7;               // position within oct

    #pragma unroll 1
    for (int t = 0; t < 16; t++) {
        unsigned cl = 0;
        int bc_own = 0;
        // branch-free relay: all lanes speculate; shfl takes lane (gbase+j)'s result
        #pragma unroll
        for (int j = 0; j < 8; j++) {
            unsigned un2 = avail2 & ~cl;
            unsigned un1 = avail  & ~cl;
            unsigned sel = un2 ? un2 : (un1 ? un1 : avail);
            int bc = __ffs(sel) - 1;
            bc_own = (own == j) ? bc : bc_own;
            unsigned cl2 = cl | (1u << bc);
            cl = __shfl_sync(0xffffffffu, cl2, gbase + j);
        }
        // commit own pick (off the relay critical path)
        unsigned mk = cmask_s[tid*9 + bc_own];
        int kk = __ffs(mk) - 1;
        mk &= mk - 1u;
        cmask_s[tid*9 + bc_own] = mk;
        if (mk == 0u)        avail  &= ~(1u << bc_own);
        if (__popc(mk) == 1) avail2 &= ~(1u << bc_own);
        pk_s[tid*16 + t] = (unsigned char)kk;
    }
    __syncthreads();

    // coalesced packed output: 512 words per (l, warp16)
    unsigned int* dst = g_cmb + (size_t)(l*16 + w) * 512;
    #pragma unroll
    for (int c = 0; c < 16; c++) {
        int wi  = c*32 + tid;                // 0..511
        int r   = wi >> 4;
        int pos = wi & 15;
        unsigned val;
        if (pos < 8) {                       // u16 offset pair for t=2*pos, 2*pos+1
            int k0 = pk_s[r*16 + 2*pos], k1 = pk_s[r*16 + 2*pos + 1];
            unsigned i0 = (unsigned)sidx_s[r*16 + k0];
            unsigned i1 = (unsigned)sidx_s[r*16 + k1];
            val = (i0 << 4) | (i1 << 20);    // byte offsets idx*16
        } else {                             // weight half2 pair for t=2k, 2k+1
            int k = pos - 8;
            int k0 = pk_s[r*16 + 2*k], k1 = pk_s[r*16 + 2*k + 1];
            __half h0 = __float2half_rn(__int_as_float(swt_s[r*16 + k0]));
            __half h1 = __float2half_rn(__int_as_float(swt_s[r*16 + k1]));
            val = (unsigned)__half_as_ushort(h0)
                | ((unsigned)__half_as_ushort(h1) << 16);
        }
        dst[wi] = val;                       // coalesced STG.32
    }
}

__device__ __forceinline__ float fast_sigmoid(float z) {
    float t;
    asm("tanh.approx.f32 %0, %1;" : "=f"(t) : "f"(0.5f * z));
    return fmaf(0.5f, t, 0.5f);
}

// ---------------- main fused kernel (identical to R15/R16's ~100-103us version) ----------------
__global__ __launch_bounds__(512, 2)
void ffn_kernel(const float* __restrict__ x,
                const float* __restrict__ bias,
                float*       __restrict__ out)
{
    extern __shared__ __half2 smem2[];
    __half2* vals2 = smem2;                               // [4096 cols][4 rp], stride 4
    char*    stage = (char*)(smem2 + WSTORE * VST);       // 16 warp-private 2560B blocks

    const unsigned int stage_u32 =
        (unsigned int)__cvta_generic_to_shared(stage);

    const int tid  = threadIdx.x;
    const int lane = tid & 31;
    const int warp = tid >> 5;          // 0..15
    const int rp   = lane & 3;          // row-pair 0..3
    const int hj   = lane >> 2;         // 0..7
    const int r0   = blockIdx.x * NR;

    // per-thread value base: gathers read *(half2*)(vbase + u16_offset)
    const char* vbase = (const char*)vals2 + rp * 4;

    // warp-private prefetch of one layer's packed table (2048B -> 128 16B chunks)
#define PREFETCH(L) { \
    const char* src = (const char*)(g_cmb + (size_t)((L)*16 + warp) * 512); \
    const unsigned int dstbase = stage_u32 + warp * STG_WARP; \
    _Pragma("unroll") for (int c = 0; c < 4; c++) { \
        int c2 = c*32 + lane; \
        unsigned int dst = dstbase + (c2 >> 2) * STG_ROW + (c2 & 3) * 16; \
        asm volatile("cp.async.ca.shared.global [%0], [%1], 16;" \
                     :: "r"(dst), "l"(src + c2*16)); } \
    asm volatile("cp.async.commit_group;" ::: "memory"); }

    PREFETCH(0)

    // ---- x tile: 4 row-pairs x 512 cols ----
    #pragma unroll
    for (int i = tid; i < NRP * NIN; i += 512) {          // 2048 half2
        int c  = i >> 2;
        int pp = i & 3;
        float a = x[(long)(r0 + 2*pp    ) * NIN + c];
        float b = x[(long)(r0 + 2*pp + 1) * NIN + c];
        vals2[c * VST + pp] = __floats2half2_rn(a, b);
    }

    int width = NIN;
    #pragma unroll 1
    for (int l = 0; l < NL; l++) {
        __syncthreads();                                  // prev layer's values visible
        asm volatile("cp.async.wait_group 0;" ::: "memory");
        __syncwarp();

        const float* brow = bias + l * NH;
        const bool last = (l == NL - 1);
        const char* wblk = stage + warp * STG_WARP;

        #pragma unroll
        for (int p = 0; p < 4; p++) {
            const int h = p * 128 + warp * 8 + hj;
            const char* rowp = wblk + (p*8 + hj) * STG_ROW;

            // 2 offset LDS.128 + 2 weight LDS.128; 8 rows on distinct bank quads
            uint4 oa = *(const uint4*)(rowp);        // u16 offset pairs t0..7
            uint4 ob = *(const uint4*)(rowp + 16);   // t8..15
            uint4 wa = *(const uint4*)(rowp + 32);   // weight half2 pairs t0..7
            uint4 wb = *(const uint4*)(rowp + 48);   // t8..15

            float ax = 0.0f, ay = 0.0f;

            // sub-chain of 4 fp16 HFMA2 steps, flushed into fp32
#define LDV(off) (*(const __half2*)(vbase + (off)))
#define SUBCHAIN(ow0, ow1, wlo, whi) { \
    __half2 hw0 = *(const __half2*)&(wlo); \
    __half2 hw1 = *(const __half2*)&(whi); \
    __half2 hacc = __hmul2(LDV((ow0) & 0xffffu), __half2half2(__low2half(hw0))); \
    hacc = __hfma2(LDV((ow0) >> 16),    __half2half2(__high2half(hw0)), hacc); \
    hacc = __hfma2(LDV((ow1) & 0xffffu), __half2half2(__low2half(hw1)),  hacc); \
    hacc = __hfma2(LDV((ow1) >> 16),    __half2half2(__high2half(hw1)), hacc); \
    float2 f = __half22float2(hacc); ax += f.x; ay += f.y; }

            SUBCHAIN(oa.x, oa.y, wa.x, wa.y)
            SUBCHAIN(oa.z, oa.w, wa.z, wa.w)
            SUBCHAIN(ob.x, ob.y, wb.x, wb.y)
            SUBCHAIN(ob.z, ob.w, wb.z, wb.w)
#undef SUBCHAIN
#undef LDV

            float b0 = __ldg(brow + h);
            float ox = fast_sigmoid(ax + b0);
            float oy = fast_sigmoid(ay + b0);

            if (!last) {
                // h mod 8 = hj -> 8 distinct quads x 4 rp -> conflict-free store
                vals2[(width + h) * VST + rp] = __floats2half2_rn(ox, oy);
            } else {
                out[(long)(r0 + 2*rp    ) * NH + h] = ox;
                out[(long)(r0 + 2*rp + 1) * NH + h] = oy;
            }
        }

        // prefetch next layer AFTER this layer's table is consumed
        if (l < NL - 1) PREFETCH(l + 1)
        width += NH;
    }
#undef PREFETCH
}

extern "C" void kernel_launch(void* const* d_in, const int* in_sizes, int n_in,
                              void* d_out, int out_size)
{
    const float* x        = (const float*)d_in[0];   // (8192, 512) f32
    const int*   link_idx = (const int*)d_in[1];     // (8, 512, 16) i32
    const float* weights  = (const float*)d_in[2];   // (8, 512, 16) f32
    const float* bias     = (const float*)d_in[3];   // (8, 512) f32
    float*       out      = (float*)d_out;           // (8192, 512) f32

    cudaFuncSetAttribute(ffn_kernel,
                         cudaFuncAttributeMaxDynamicSharedMemorySize, SMEM_BYTES);

    sched_kernel<<<NL*16, 32>>>(link_idx, weights);
    ffn_kernel<<<NB / NR, 512, SMEM_BYTES>>>(x, bias, out);
}